// round 15
// baseline (speedup 1.0000x reference)
#include <cuda_runtime.h>
#include <cuda_fp16.h>
#include <math.h>
#include <stdint.h>

// ---------------------------------------------------------------------------
// GPT forward. fp16 mma.sync tensor cores, 3-stage pipelined GEMM.
// qkv/fc: 128x128 CTA tile @ 2 CTAs/SM. proj/fc2: 64x128 @ 3 CTAs/SM.
// Flash attn 64 q-rows @ occ 3. f2h STG.128 + stream-overlapped conversion
// of layers 1..3 weights under layer-0 compute (graph fork/join).
// B=2, T=1024, C=1024, L=4, H=16, HD=64, V=50257. Unmasked attention.
// ---------------------------------------------------------------------------

#define Bv 2
#define Tv 1024
#define Cv 1024
#define Lv 4
#define Hv 16
#define HDv 64
#define Vv 50257
#define BTv 2048
#define KQKV (3 * Cv)

// ---- scratch ---------------------------------------------------------------
__device__ float  g_x[BTv * Cv];
__device__ __half g_ln[BTv * Cv];
__device__ __half g_qkv[BTv * 3 * Cv];
__device__ __half g_o[BTv * Cv];
__device__ __half g_fc[BTv * 4 * Cv];
__device__ float  g_xf[Bv * Cv];
__device__ __half g_wa[Lv * 3 * Cv * Cv];
__device__ __half g_wp[Lv * Cv * Cv];
__device__ __half g_wf[Lv * 4 * Cv * Cv];
__device__ __half g_wf2[Lv * 4 * Cv * Cv];

// ---- PTX helpers ------------------------------------------------------------
__device__ __forceinline__ uint32_t cvta_s(const void* p) {
    return (uint32_t)__cvta_generic_to_shared(p);
}
__device__ __forceinline__ void cp_async16(uint32_t s, const void* g) {
    asm volatile("cp.async.cg.shared.global [%0], [%1], 16;" ::"r"(s), "l"(g));
}
__device__ __forceinline__ void cp_commit() {
    asm volatile("cp.async.commit_group;");
}
template <int N>
__device__ __forceinline__ void cp_wait() {
    asm volatile("cp.async.wait_group %0;" ::"n"(N));
}
__device__ __forceinline__ void ldsm_x4(uint32_t& r0, uint32_t& r1, uint32_t& r2,
                                        uint32_t& r3, uint32_t a) {
    asm volatile("ldmatrix.sync.aligned.m8n8.x4.shared.b16 {%0,%1,%2,%3}, [%4];"
                 : "=r"(r0), "=r"(r1), "=r"(r2), "=r"(r3) : "r"(a));
}
__device__ __forceinline__ void ldsm_x4t(uint32_t& r0, uint32_t& r1, uint32_t& r2,
                                         uint32_t& r3, uint32_t a) {
    asm volatile("ldmatrix.sync.aligned.m8n8.x4.trans.shared.b16 {%0,%1,%2,%3}, [%4];"
                 : "=r"(r0), "=r"(r1), "=r"(r2), "=r"(r3) : "r"(a));
}
__device__ __forceinline__ void mma16816(float* c, uint32_t a0, uint32_t a1,
                                         uint32_t a2, uint32_t a3, uint32_t b0,
                                         uint32_t b1) {
    asm volatile(
        "mma.sync.aligned.m16n8k16.row.col.f32.f16.f16.f32 "
        "{%0,%1,%2,%3}, {%4,%5,%6,%7}, {%8,%9}, {%0,%1,%2,%3};"
        : "+f"(c[0]), "+f"(c[1]), "+f"(c[2]), "+f"(c[3])
        : "r"(a0), "r"(a1), "r"(a2), "r"(a3), "r"(b0), "r"(b1));
}
__device__ __forceinline__ uint32_t pack_half2(float a, float b) {
    __half2 h = __floats2half2_rn(a, b);
    return *reinterpret_cast<uint32_t*>(&h);
}
// swizzled half-offset; tile row = 64 halves (8 x 16B chunks)
__device__ __forceinline__ uint32_t sw(int row, int kcol) {
    return (uint32_t)((row << 6) + ((((kcol >> 3) ^ (row & 7)) << 3) + (kcol & 7)));
}
__device__ __forceinline__ float gelu_f(float x) {
    return 0.5f * x * (1.0f + erff(x * 0.70710678118654752f));
}

// ---------------------------------------------------------------------------
// fp32->fp16 weight conversion for a contiguous layer range [l0, l1) of all
// four weight groups. 2 float4 loads -> 1 uint4 (STG.128) store per thread.
// Per-layer sizes (float4 units): wa 3*C*C/4, wp C*C/4, wf/wf2 4*C*C/4.
// ---------------------------------------------------------------------------
#define L4A (3 * Cv * Cv / 4)
#define L4P (Cv * Cv / 4)
#define L4F (4 * Cv * Cv / 4)
#define L4TOT (L4A + L4P + 2 * L4F)  // per-layer float4 count (3M)

__global__ void f2h_range_kernel(const float* __restrict__ sa, __half* __restrict__ da,
                                 const float* __restrict__ sp, __half* __restrict__ dp,
                                 const float* __restrict__ sf, __half* __restrict__ df,
                                 const float* __restrict__ sf2, __half* __restrict__ df2,
                                 int l0, int nl) {
    long long i = (long long)(blockIdx.x * blockDim.x + threadIdx.x) * 2;
    long long tot = (long long)nl * L4TOT;
    if (i >= tot) return;
    int layer = (int)(i / L4TOT) + l0;
    long long r = i % L4TOT;
    const float* s;
    __half* d;
    long long off;
    if (r < L4A) {
        s = sa; d = da; off = (long long)layer * L4A + r;
    } else if (r < L4A + L4P) {
        s = sp; d = dp; off = (long long)layer * L4P + (r - L4A);
    } else if (r < L4A + L4P + L4F) {
        s = sf; d = df; off = (long long)layer * L4F + (r - L4A - L4P);
    } else {
        s = sf2; d = df2; off = (long long)layer * L4F + (r - L4A - L4P - L4F);
    }
    const float4* s4 = (const float4*)s;
    float4 v0 = s4[off], v1 = s4[off + 1];
    uint4 pk;
    pk.x = pack_half2(v0.x, v0.y);
    pk.y = pack_half2(v0.z, v0.w);
    pk.z = pack_half2(v1.x, v1.y);
    pk.w = pack_half2(v1.z, v1.w);
    *(uint4*)(d + off * 4) = pk;
}

__global__ void embed_kernel(const int* __restrict__ idx,
                             const float* __restrict__ wte,
                             const float* __restrict__ wpe,
                             float* __restrict__ x) {
    int row = blockIdx.x;
    int t = row & (Tv - 1);
    int tok = idx[row];
    float4 va = ((const float4*)(wte + (size_t)tok * Cv))[threadIdx.x];
    float4 vp = ((const float4*)(wpe + (size_t)t * Cv))[threadIdx.x];
    ((float4*)(x + (size_t)row * Cv))[threadIdx.x] =
        make_float4(va.x + vp.x, va.y + vp.y, va.z + vp.z, va.w + vp.w);
}

// ---------------------------------------------------------------------------
template <typename OT>
__global__ void layernorm_kernel(const float* __restrict__ in, size_t in_stride,
                                 const float* __restrict__ w,
                                 const float* __restrict__ b,
                                 OT* __restrict__ out, size_t out_stride) {
    const float* p = in + (size_t)blockIdx.x * in_stride;
    int tid = threadIdx.x;
    float4 v = ((const float4*)p)[tid];
    float s = v.x + v.y + v.z + v.w;
    float ss = v.x * v.x + v.y * v.y + v.z * v.z + v.w * v.w;

    __shared__ float sm1[8], sm2[8];
    int lane = tid & 31, wid = tid >> 5;
#pragma unroll
    for (int o = 16; o > 0; o >>= 1) {
        s += __shfl_down_sync(0xffffffffu, s, o);
        ss += __shfl_down_sync(0xffffffffu, ss, o);
    }
    if (lane == 0) { sm1[wid] = s; sm2[wid] = ss; }
    __syncthreads();
    if (wid == 0) {
        s = (lane < 8) ? sm1[lane] : 0.f;
        ss = (lane < 8) ? sm2[lane] : 0.f;
#pragma unroll
        for (int o = 4; o > 0; o >>= 1) {
            s += __shfl_down_sync(0xffffffffu, s, o);
            ss += __shfl_down_sync(0xffffffffu, ss, o);
        }
        if (lane == 0) { sm1[0] = s; sm2[0] = ss; }
    }
    __syncthreads();
    float mean = sm1[0] * (1.0f / Cv);
    float var = sm2[0] * (1.0f / Cv) - mean * mean;
    float rstd = rsqrtf(var + 1e-5f);
    float4 w4 = ((const float4*)w)[tid];
    float4 b4 = ((const float4*)b)[tid];
    float y0 = (v.x - mean) * rstd * w4.x + b4.x;
    float y1 = (v.y - mean) * rstd * w4.y + b4.y;
    float y2 = (v.z - mean) * rstd * w4.z + b4.z;
    float y3 = (v.w - mean) * rstd * w4.w + b4.w;
    OT* op = out + (size_t)blockIdx.x * out_stride + tid * 4;
    if (sizeof(OT) == 2) {
        __half2* hp = (__half2*)op;
        hp[0] = __floats2half2_rn(y0, y1);
        hp[1] = __floats2half2_rn(y2, y3);
    } else {
        float4* fp = (float4*)op;
        *fp = make_float4(y0, y1, y2, y3);
    }
}

// ---------------------------------------------------------------------------
// Dense HGEMM: out = A @ W^T + bias. CTA tile BMT x 128, BK=64, 3-stage
// cp.async pipeline, one barrier/stage. 256 threads, 8 warps (4m x 2n),
// rotating B-fragment buffer. BMT=128 -> 2 CTAs/SM, BMT=64 -> 3 CTAs/SM.
// EPI 0: half out. 1: fp32 residual in-place. 2: gelu half out.
// ---------------------------------------------------------------------------
#define BN 128
#define BKH 64

template <int EPI, int BMT>
__global__ __launch_bounds__(256, (BMT == 64) ? 3 : 2) void hgemm_kernel(
    const __half* __restrict__ A, const __half* __restrict__ W,
    const float* __restrict__ bias, float* __restrict__ resio,
    __half* __restrict__ outh, int M, int N, int K) {
    constexpr int S = 3;
    constexpr int MT = BMT / 64;
    constexpr int ASTG = BMT * BKH;
    constexpr int BSTG = BN * BKH;
    extern __shared__ __align__(16) __half smx[];
    __half* As = smx;
    __half* Bs = smx + S * ASTG;
    const int tid = threadIdx.x;
    const int lane = tid & 31;
    const int w = tid >> 5;
    const int wm = w >> 1;
    const int wn = w & 1;

    const __half* Ab = A + (size_t)(blockIdx.y * BMT) * K;
    const __half* Wb = W + (size_t)(blockIdx.x * BN) * K;
    uint32_t sA = cvta_s(As);
    uint32_t sB = cvta_s(Bs);

    float acc[MT][8][4];
#pragma unroll
    for (int i = 0; i < MT; i++)
#pragma unroll
        for (int j = 0; j < 8; j++)
#pragma unroll
            for (int q = 0; q < 4; q++) acc[i][j][q] = 0.f;

    const int KT = K / BKH;

    auto load_stage = [&](int kt) {
        int stg = kt % S;
        int koff = kt * BKH;
        uint32_t dA = sA + stg * ASTG * 2;
        uint32_t dB = sB + stg * BSTG * 2;
#pragma unroll
        for (int i = 0; i < BMT / 32; i++) {
            int g = tid + i * 256; int r = g >> 3; int c = g & 7;
            cp_async16(dA + sw(r, c * 8) * 2, Ab + (size_t)r * K + koff + c * 8);
        }
#pragma unroll
        for (int i = 0; i < BN / 32; i++) {
            int g = tid + i * 256; int r = g >> 3; int c = g & 7;
            cp_async16(dB + sw(r, c * 8) * 2, Wb + (size_t)r * K + koff + c * 8);
        }
        cp_commit();
    };

    load_stage(0);
    load_stage(1);

    auto bf_addr = [&](uint32_t bB, int k0, int np) -> uint32_t {
        int r = wn * 64 + np * 16 + (lane & 7) + (((lane >> 4) & 1) << 3);
        int kc = k0 + (((lane >> 3) & 1) << 3);
        return bB + sw(r, kc) * 2;
    };

    for (int kt = 0; kt < KT; ++kt) {
        if (kt == KT - 1) cp_wait<0>(); else cp_wait<1>();
        __syncthreads();
        if (kt + 2 < KT) load_stage(kt + 2);

        int stg = kt % S;
        uint32_t aB = sA + (uint32_t)(stg * ASTG * 2);
        uint32_t bB = sB + (uint32_t)(stg * BSTG * 2);
#pragma unroll
        for (int ks = 0; ks < 4; ++ks) {
            int k0 = ks * 16;
            uint32_t af[MT][4];
#pragma unroll
            for (int mt = 0; mt < MT; ++mt) {
                int r = wm * (MT * 16) + mt * 16 + ((lane >> 3) & 1) * 8 + (lane & 7);
                int kc = k0 + ((lane >> 4) << 3);
                ldsm_x4(af[mt][0], af[mt][1], af[mt][2], af[mt][3],
                        aB + sw(r, kc) * 2);
            }
            uint32_t bf0[4];
            ldsm_x4(bf0[0], bf0[1], bf0[2], bf0[3], bf_addr(bB, k0, 0));
#pragma unroll
            for (int np = 0; np < 4; ++np) {
                uint32_t bf1[4];
                if (np < 3)
                    ldsm_x4(bf1[0], bf1[1], bf1[2], bf1[3], bf_addr(bB, k0, np + 1));
#pragma unroll
                for (int mt = 0; mt < MT; ++mt) {
                    mma16816(acc[mt][2 * np], af[mt][0], af[mt][1], af[mt][2],
                             af[mt][3], bf0[0], bf0[1]);
                    mma16816(acc[mt][2 * np + 1], af[mt][0], af[mt][1], af[mt][2],
                             af[mt][3], bf0[2], bf0[3]);
                }
                if (np < 3) {
                    bf0[0] = bf1[0]; bf0[1] = bf1[1];
                    bf0[2] = bf1[2]; bf0[3] = bf1[3];
                }
            }
        }
    }

    int g = lane >> 2, t = lane & 3;
#pragma unroll
    for (int mt = 0; mt < MT; ++mt) {
        int r0 = blockIdx.y * BMT + wm * (MT * 16) + mt * 16 + g;
#pragma unroll
        for (int nt = 0; nt < 8; ++nt) {
            int col = blockIdx.x * BN + wn * 64 + nt * 8 + 2 * t;
            float b0 = bias[col], b1 = bias[col + 1];
            float d0 = acc[mt][nt][0] + b0, d1 = acc[mt][nt][1] + b1;
            float d2 = acc[mt][nt][2] + b0, d3 = acc[mt][nt][3] + b1;
            if (EPI == 0) {
                *(__half2*)&outh[(size_t)r0 * N + col] = __floats2half2_rn(d0, d1);
                *(__half2*)&outh[(size_t)(r0 + 8) * N + col] = __floats2half2_rn(d2, d3);
            } else if (EPI == 1) {
                float2* p0 = (float2*)&resio[(size_t)r0 * N + col];
                float2 v0 = *p0; v0.x += d0; v0.y += d1; *p0 = v0;
                float2* p1 = (float2*)&resio[(size_t)(r0 + 8) * N + col];
                float2 v1 = *p1; v1.x += d2; v1.y += d3; *p1 = v1;
            } else {
                *(__half2*)&outh[(size_t)r0 * N + col] =
                    __floats2half2_rn(gelu_f(d0), gelu_f(d1));
                *(__half2*)&outh[(size_t)(r0 + 8) * N + col] =
                    __floats2half2_rn(gelu_f(d2), gelu_f(d3));
            }
        }
    }
}

// ---------------------------------------------------------------------------
// Fused flash attention (unmasked). Per CTA: 64 q rows of one (b,h).
// 128 threads = 4 warps, occ 3.
// ---------------------------------------------------------------------------
#define FBR 64
#define FBC 128
#define FJT (Tv / FBC)  // 8

__global__ __launch_bounds__(128, 3) void flash_kernel(
    const __half* __restrict__ qkv, __half* __restrict__ o) {
    extern __shared__ __align__(16) __half fsm[];
    __half* Qs = fsm;
    __half* Ks = fsm + FBR * HDv;
    __half* Vs = Ks + 2 * FBC * HDv;
    const uint32_t sQ = cvta_s(Qs), sK = cvta_s(Ks), sV = cvta_s(Vs);
    const int tid = threadIdx.x;
    const int lane = tid & 31;
    const int w = tid >> 5;

    const int z = blockIdx.y, b = z >> 4, h = z & 15;
    const int i0 = blockIdx.x * FBR;
    const __half* qb = qkv + ((size_t)(b * Tv + i0)) * KQKV + h * HDv;
    const __half* kb = qkv + ((size_t)b * Tv) * KQKV + Cv + h * HDv;
    const __half* vb = kb + Cv;

    auto load_kv = [&](int jt) {
        int buf = jt & 1;
        int j0 = jt * FBC;
#pragma unroll
        for (int i = 0; i < 8; i++) {
            int g = tid + i * 128; int r = g >> 3; int c = g & 7;
            cp_async16(sK + (buf * FBC * HDv + sw(r, c * 8)) * 2,
                       kb + (size_t)(j0 + r) * KQKV + c * 8);
            cp_async16(sV + (buf * FBC * HDv + sw(r, c * 8)) * 2,
                       vb + (size_t)(j0 + r) * KQKV + c * 8);
        }
        cp_commit();
    };

#pragma unroll
    for (int i = 0; i < 4; i++) {
        int g = tid + i * 128; int r = g >> 3; int c = g & 7;
        cp_async16(sQ + sw(r, c * 8) * 2, qb + (size_t)r * KQKV + c * 8);
    }
    load_kv(0);

    float m0 = -1e30f, m1 = -1e30f, s0 = 0.f, s1 = 0.f;
    float acc_o[8][4];
#pragma unroll
    for (int i = 0; i < 8; i++)
#pragma unroll
        for (int q = 0; q < 4; q++) acc_o[i][q] = 0.f;

    uint32_t qf[4][4];

    for (int jt = 0; jt < FJT; ++jt) {
        int cur = jt & 1;
        cp_wait<0>();
        __syncthreads();
        if (jt + 1 < FJT) load_kv(jt + 1);

        if (jt == 0) {
#pragma unroll
            for (int ks = 0; ks < 4; ++ks) {
                int r = w * 16 + ((lane >> 3) & 1) * 8 + (lane & 7);
                int kc = ks * 16 + ((lane >> 4) << 3);
                ldsm_x4(qf[ks][0], qf[ks][1], qf[ks][2], qf[ks][3],
                        sQ + sw(r, kc) * 2);
            }
        }

        uint32_t kB = sK + (uint32_t)(cur * FBC * HDv * 2);
        uint32_t vB = sV + (uint32_t)(cur * FBC * HDv * 2);

        float acc_s[16][4];
#pragma unroll
        for (int i = 0; i < 16; i++)
#pragma unroll
            for (int q = 0; q < 4; q++) acc_s[i][q] = 0.f;

#pragma unroll
        for (int ks = 0; ks < 4; ++ks) {
            int k0 = ks * 16;
#pragma unroll
            for (int ntp = 0; ntp < 8; ++ntp) {
                uint32_t b0, b1, b2, b3;
                int r = ntp * 16 + (lane >> 4) * 8 + (lane & 7);
                int kc = k0 + ((lane >> 3) & 1) * 8;
                ldsm_x4(b0, b1, b2, b3, kB + sw(r, kc) * 2);
                mma16816(acc_s[2 * ntp], qf[ks][0], qf[ks][1], qf[ks][2],
                         qf[ks][3], b0, b1);
                mma16816(acc_s[2 * ntp + 1], qf[ks][0], qf[ks][1], qf[ks][2],
                         qf[ks][3], b2, b3);
            }
        }

        float m0n = m0, m1n = m1;
#pragma unroll
        for (int nt = 0; nt < 16; ++nt) {
            acc_s[nt][0] *= 0.125f; acc_s[nt][1] *= 0.125f;
            acc_s[nt][2] *= 0.125f; acc_s[nt][3] *= 0.125f;
            m0n = fmaxf(m0n, fmaxf(acc_s[nt][0], acc_s[nt][1]));
            m1n = fmaxf(m1n, fmaxf(acc_s[nt][2], acc_s[nt][3]));
        }
#pragma unroll
        for (int off = 1; off <= 2; off <<= 1) {
            m0n = fmaxf(m0n, __shfl_xor_sync(0xffffffffu, m0n, off));
            m1n = fmaxf(m1n, __shfl_xor_sync(0xffffffffu, m1n, off));
        }
        float alpha0 = __expf(m0 - m0n);
        float alpha1 = __expf(m1 - m1n);
        m0 = m0n; m1 = m1n;

        float r0 = 0.f, r1 = 0.f;
#pragma unroll
        for (int nt = 0; nt < 16; ++nt) {
            acc_s[nt][0] = __expf(acc_s[nt][0] - m0n);
            acc_s[nt][1] = __expf(acc_s[nt][1] - m0n);
            acc_s[nt][2] = __expf(acc_s[nt][2] - m1n);
            acc_s[nt][3] = __expf(acc_s[nt][3] - m1n);
            r0 += acc_s[nt][0] + acc_s[nt][1];
            r1 += acc_s[nt][2] + acc_s[nt][3];
        }
#pragma unroll
        for (int off = 1; off <= 2; off <<= 1) {
            r0 += __shfl_xor_sync(0xffffffffu, r0, off);
            r1 += __shfl_xor_sync(0xffffffffu, r1, off);
        }
        s0 = s0 * alpha0 + r0;
        s1 = s1 * alpha1 + r1;

#pragma unroll
        for (int nt = 0; nt < 8; ++nt) {
            acc_o[nt][0] *= alpha0; acc_o[nt][1] *= alpha0;
            acc_o[nt][2] *= alpha1; acc_o[nt][3] *= alpha1;
        }

#pragma unroll
        for (int kc = 0; kc < 8; ++kc) {
            uint32_t a0 = pack_half2(acc_s[2 * kc][0], acc_s[2 * kc][1]);
            uint32_t a1 = pack_half2(acc_s[2 * kc][2], acc_s[2 * kc][3]);
            uint32_t a2 = pack_half2(acc_s[2 * kc + 1][0], acc_s[2 * kc + 1][1]);
            uint32_t a3 = pack_half2(acc_s[2 * kc + 1][2], acc_s[2 * kc + 1][3]);
#pragma unroll
            for (int dp = 0; dp < 4; ++dp) {
                uint32_t b0, b1, b2, b3;
                int r = kc * 16 + ((lane >> 3) & 1) * 8 + (lane & 7);
                int c = dp * 16 + (lane >> 4) * 8;
                ldsm_x4t(b0, b1, b2, b3, vB + sw(r, c) * 2);
                mma16816(acc_o[2 * dp], a0, a1, a2, a3, b0, b1);
                mma16816(acc_o[2 * dp + 1], a0, a1, a2, a3, b2, b3);
            }
        }
    }

    float inv0 = 1.0f / s0, inv1 = 1.0f / s1;
    int g = lane >> 2, t = lane & 3;
    int ro0 = i0 + w * 16 + g;
#pragma unroll
    for (int nt = 0; nt < 8; ++nt) {
        int d = nt * 8 + 2 * t;
        *(__half2*)&o[((size_t)b * Tv + ro0) * Cv + h * HDv + d] =
            __floats2half2_rn(acc_o[nt][0] * inv0, acc_o[nt][1] * inv0);
        *(__half2*)&o[((size_t)b * Tv + ro0 + 8) * Cv + h * HDv + d] =
            __floats2half2_rn(acc_o[nt][2] * inv1, acc_o[nt][3] * inv1);
    }
}

// ---------------------------------------------------------------------------
// logits GEMV (fp32, tied wte). One warp per vocab row, both batch rows.
// ---------------------------------------------------------------------------
__global__ void logits_kernel(const float* __restrict__ xf,
                              const float* __restrict__ wte,
                              float* __restrict__ out) {
    int warp = (blockIdx.x * blockDim.x + threadIdx.x) >> 5;
    int lane = threadIdx.x & 31;
    if (warp >= Vv) return;
    const float4* w4 = (const float4*)(wte + (size_t)warp * Cv);
    const float4* x0 = (const float4*)xf;
    const float4* x1 = (const float4*)(xf + Cv);
    float s0 = 0.f, s1 = 0.f;
#pragma unroll
    for (int i = lane; i < Cv / 4; i += 32) {
        float4 w = w4[i];
        float4 a = x0[i];
        float4 c = x1[i];
        s0 += w.x * a.x + w.y * a.y + w.z * a.z + w.w * a.w;
        s1 += w.x * c.x + w.y * c.y + w.z * c.z + w.w * c.w;
    }
#pragma unroll
    for (int o = 16; o > 0; o >>= 1) {
        s0 += __shfl_down_sync(0xffffffffu, s0, o);
        s1 += __shfl_down_sync(0xffffffffu, s1, o);
    }
    if (lane == 0) {
        out[warp] = s0;
        out[Vv + warp] = s1;
    }
}

// ---------------------------------------------------------------------------
extern "C" void kernel_launch(void* const* d_in, const int* in_sizes, int n_in,
                              void* d_out, int out_size) {
    const int* idx = (const int*)d_in[0];
    const float* wte = (const float*)d_in[1];
    const float* wpe = (const float*)d_in[2];
    const float* ln1_w = (const float*)d_in[3];
    const float* ln1_b = (const float*)d_in[4];
    const float* attn_w = (const float*)d_in[5];
    const float* attn_b = (const float*)d_in[6];
    const float* proj_w = (const float*)d_in[7];
    const float* proj_b = (const float*)d_in[8];
    const float* ln2_w = (const float*)d_in[9];
    const float* ln2_b = (const float*)d_in[10];
    const float* fc_w = (const float*)d_in[11];
    const float* fc_b = (const float*)d_in[12];
    const float* fc2_w = (const float*)d_in[13];
    const float* fc2_b = (const float*)d_in[14];
    const float* lnf_w = (const float*)d_in[15];
    const float* lnf_b = (const float*)d_in[16];
    float* out = (float*)d_out;

    float* x;    cudaGetSymbolAddress((void**)&x, g_x);
    __half* ln;  cudaGetSymbolAddress((void**)&ln, g_ln);
    __half* qkv; cudaGetSymbolAddress((void**)&qkv, g_qkv);
    __half* o;   cudaGetSymbolAddress((void**)&o, g_o);
    __half* fc;  cudaGetSymbolAddress((void**)&fc, g_fc);
    float* xf;   cudaGetSymbolAddress((void**)&xf, g_xf);
    __half* wa;  cudaGetSymbolAddress((void**)&wa, g_wa);
    __half* wp;  cudaGetSymbolAddress((void**)&wp, g_wp);
    __half* wf;  cudaGetSymbolAddress((void**)&wf, g_wf);
    __half* wf2; cudaGetSymbolAddress((void**)&wf2, g_wf2);

    const int HSM128 = 3 * (128 * BKH + BN * BKH) * 2;  // 98304
    const int HSM64 = 3 * (64 * BKH + BN * BKH) * 2;    // 73728
    const int FSM = (FBR * HDv + 4 * FBC * HDv) * 2;    // 73728
    cudaFuncSetAttribute(hgemm_kernel<0, 128>, cudaFuncAttributeMaxDynamicSharedMemorySize, HSM128);
    cudaFuncSetAttribute(hgemm_kernel<2, 128>, cudaFuncAttributeMaxDynamicSharedMemorySize, HSM128);
    cudaFuncSetAttribute(hgemm_kernel<1, 64>, cudaFuncAttributeMaxDynamicSharedMemorySize, HSM64);
    cudaFuncSetAttribute(flash_kernel, cudaFuncAttributeMaxDynamicSharedMemorySize, FSM);

    // side stream + events (created once; deterministic work every call)
    static cudaStream_t s2 = nullptr;
    static cudaEvent_t evFork = nullptr, evJoin = nullptr;
    if (s2 == nullptr) {
        cudaStreamCreateWithFlags(&s2, cudaStreamNonBlocking);
        cudaEventCreateWithFlags(&evFork, cudaEventDisableTiming);
        cudaEventCreateWithFlags(&evJoin, cudaEventDisableTiming);
    }

    // fork: convert layers 1..3 weights on s2, overlapped with layer-0 compute
    cudaEventRecord(evFork, 0);
    cudaStreamWaitEvent(s2, evFork, 0);
    {
        long long tot = 3LL * L4TOT / 2;  // threads for layers 1..3
        f2h_range_kernel<<<(unsigned)((tot + 255) / 256), 256, 0, s2>>>(
            attn_w, wa, proj_w, wp, fc_w, wf, fc2_w, wf2, 1, 3);
        cudaEventRecord(evJoin, s2);
    }
    // layer-0 weights on the main stream (critical path)
    {
        long long tot = (long long)L4TOT / 2;
        f2h_range_kernel<<<(unsigned)((tot + 255) / 256), 256>>>(
            attn_w, wa, proj_w, wp, fc_w, wf, fc2_w, wf2, 0, 1);
    }

    embed_kernel<<<BTv, 256>>>(idx, wte, wpe, x);

    for (int l = 0; l < Lv; ++l) {
        if (l == 1) cudaStreamWaitEvent(0, evJoin, 0);  // join before layer 1
        layernorm_kernel<__half><<<BTv, 256>>>(x, Cv, ln1_w + l * Cv, ln1_b + l * Cv, ln, Cv);
        hgemm_kernel<0, 128><<<dim3(3 * Cv / BN, BTv / 128), 256, HSM128>>>(
            ln, wa + (size_t)l * 3 * Cv * Cv, attn_b + l * 3 * Cv, nullptr, qkv,
            BTv, 3 * Cv, Cv);
        flash_kernel<<<dim3(Tv / FBR, Bv * Hv), 128, FSM>>>(qkv, o);
        hgemm_kernel<1, 64><<<dim3(Cv / BN, BTv / 64), 256, HSM64>>>(
            o, wp + (size_t)l * Cv * Cv, proj_b + l * Cv, x, nullptr, BTv, Cv, Cv);
        layernorm_kernel<__half><<<BTv, 256>>>(x, Cv, ln2_w + l * Cv, ln2_b + l * Cv, ln, Cv);
        hgemm_kernel<2, 128><<<dim3(4 * Cv / BN, BTv / 128), 256, HSM128>>>(
            ln, wf + (size_t)l * 4 * Cv * Cv, fc_b + l * 4 * Cv, nullptr, fc, BTv,
            4 * Cv, Cv);
        hgemm_kernel<1, 64><<<dim3(Cv / BN, BTv / 64), 256, HSM64>>>(
            fc, wf2 + (size_t)l * 4 * Cv * Cv, fc2_b + l * Cv, x, nullptr, BTv, Cv,
            4 * Cv);
    }

    layernorm_kernel<float><<<Bv, 256>>>(x + (size_t)(Tv - 1) * Cv, (size_t)Tv * Cv,
                                         lnf_w, lnf_b, xf, Cv);
    int blocks = (Vv * 32 + 255) / 256;
    logits_kernel<<<blocks, 256>>>(xf, wte, out);
}

// round 16
// speedup vs baseline: 1.0065x; 1.0065x over previous
#include <cuda_runtime.h>
#include <cuda_fp16.h>
#include <math.h>
#include <stdint.h>

// ---------------------------------------------------------------------------
// GPT forward. fp16 mma.sync tensor cores, 3-stage pipelined GEMM.
// qkv/fc: 128x128 CTA tile @ 2 CTAs/SM. proj/fc2: 64x128 @ 3 CTAs/SM.
// Flash attn 64 q-rows @ occ 3. f2h STG.128. Warp-per-row layernorm
// (no block barriers). B=2,T=1024,C=1024,L=4,H=16,HD=64,V=50257. Unmasked.
// ---------------------------------------------------------------------------

#define Bv 2
#define Tv 1024
#define Cv 1024
#define Lv 4
#define Hv 16
#define HDv 64
#define Vv 50257
#define BTv 2048
#define KQKV (3 * Cv)

// ---- scratch ---------------------------------------------------------------
__device__ float  g_x[BTv * Cv];
__device__ __half g_ln[BTv * Cv];
__device__ __half g_qkv[BTv * 3 * Cv];
__device__ __half g_o[BTv * Cv];
__device__ __half g_fc[BTv * 4 * Cv];
__device__ float  g_xf[Bv * Cv];
__device__ __half g_wa[Lv * 3 * Cv * Cv];
__device__ __half g_wp[Lv * Cv * Cv];
__device__ __half g_wf[Lv * 4 * Cv * Cv];
__device__ __half g_wf2[Lv * 4 * Cv * Cv];

// ---- PTX helpers ------------------------------------------------------------
__device__ __forceinline__ uint32_t cvta_s(const void* p) {
    return (uint32_t)__cvta_generic_to_shared(p);
}
__device__ __forceinline__ void cp_async16(uint32_t s, const void* g) {
    asm volatile("cp.async.cg.shared.global [%0], [%1], 16;" ::"r"(s), "l"(g));
}
__device__ __forceinline__ void cp_commit() {
    asm volatile("cp.async.commit_group;");
}
template <int N>
__device__ __forceinline__ void cp_wait() {
    asm volatile("cp.async.wait_group %0;" ::"n"(N));
}
__device__ __forceinline__ void ldsm_x4(uint32_t& r0, uint32_t& r1, uint32_t& r2,
                                        uint32_t& r3, uint32_t a) {
    asm volatile("ldmatrix.sync.aligned.m8n8.x4.shared.b16 {%0,%1,%2,%3}, [%4];"
                 : "=r"(r0), "=r"(r1), "=r"(r2), "=r"(r3) : "r"(a));
}
__device__ __forceinline__ void ldsm_x4t(uint32_t& r0, uint32_t& r1, uint32_t& r2,
                                         uint32_t& r3, uint32_t a) {
    asm volatile("ldmatrix.sync.aligned.m8n8.x4.trans.shared.b16 {%0,%1,%2,%3}, [%4];"
                 : "=r"(r0), "=r"(r1), "=r"(r2), "=r"(r3) : "r"(a));
}
__device__ __forceinline__ void mma16816(float* c, uint32_t a0, uint32_t a1,
                                         uint32_t a2, uint32_t a3, uint32_t b0,
                                         uint32_t b1) {
    asm volatile(
        "mma.sync.aligned.m16n8k16.row.col.f32.f16.f16.f32 "
        "{%0,%1,%2,%3}, {%4,%5,%6,%7}, {%8,%9}, {%0,%1,%2,%3};"
        : "+f"(c[0]), "+f"(c[1]), "+f"(c[2]), "+f"(c[3])
        : "r"(a0), "r"(a1), "r"(a2), "r"(a3), "r"(b0), "r"(b1));
}
__device__ __forceinline__ uint32_t pack_half2(float a, float b) {
    __half2 h = __floats2half2_rn(a, b);
    return *reinterpret_cast<uint32_t*>(&h);
}
// swizzled half-offset; tile row = 64 halves (8 x 16B chunks)
__device__ __forceinline__ uint32_t sw(int row, int kcol) {
    return (uint32_t)((row << 6) + ((((kcol >> 3) ^ (row & 7)) << 3) + (kcol & 7)));
}
__device__ __forceinline__ float gelu_f(float x) {
    return 0.5f * x * (1.0f + erff(x * 0.70710678118654752f));
}

// ---------------------------------------------------------------------------
// fused fp32->fp16 weight conversion: 2 float4 loads -> 1 uint4 store/thread.
// ---------------------------------------------------------------------------
#define N4A (Lv * 3 * Cv * Cv / 4)
#define N4P (Lv * Cv * Cv / 4)
#define N4F (Lv * 4 * Cv * Cv / 4)
#define N4TOT (N4A + N4P + 2 * N4F)

__global__ void f2h_all_kernel(const float* __restrict__ sa, __half* __restrict__ da,
                               const float* __restrict__ sp, __half* __restrict__ dp,
                               const float* __restrict__ sf, __half* __restrict__ df,
                               const float* __restrict__ sf2, __half* __restrict__ df2) {
    int i = (blockIdx.x * blockDim.x + threadIdx.x) * 2;
    if (i >= N4TOT) return;
    const float* s;
    __half* d;
    if (i < N4A) {
        s = sa; d = da;
    } else if (i < N4A + N4P) {
        i -= N4A; s = sp; d = dp;
    } else if (i < N4A + N4P + N4F) {
        i -= N4A + N4P; s = sf; d = df;
    } else {
        i -= N4A + N4P + N4F; s = sf2; d = df2;
    }
    const float4* s4 = (const float4*)s;
    float4 v0 = s4[i], v1 = s4[i + 1];
    uint4 pk;
    pk.x = pack_half2(v0.x, v0.y);
    pk.y = pack_half2(v0.z, v0.w);
    pk.z = pack_half2(v1.x, v1.y);
    pk.w = pack_half2(v1.z, v1.w);
    *(uint4*)(d + (size_t)i * 4) = pk;
}

__global__ void embed_kernel(const int* __restrict__ idx,
                             const float* __restrict__ wte,
                             const float* __restrict__ wpe,
                             float* __restrict__ x) {
    int row = blockIdx.x;
    int t = row & (Tv - 1);
    int tok = idx[row];
    float4 va = ((const float4*)(wte + (size_t)tok * Cv))[threadIdx.x];
    float4 vp = ((const float4*)(wpe + (size_t)t * Cv))[threadIdx.x];
    ((float4*)(x + (size_t)row * Cv))[threadIdx.x] =
        make_float4(va.x + vp.x, va.y + vp.y, va.z + vp.z, va.w + vp.w);
}

// ---------------------------------------------------------------------------
// Warp-per-row layernorm: 8 warps/block = 8 rows, grid = rows/8.
// Lane holds 8 float4 (32 floats) of its row; pure shfl.xor reduction;
// no block barriers, no smem.
// ---------------------------------------------------------------------------
template <typename OT>
__global__ __launch_bounds__(256) void layernorm_kernel(
    const float* __restrict__ in, size_t in_stride, const float* __restrict__ w,
    const float* __restrict__ b, OT* __restrict__ out, size_t out_stride,
    int nrows) {
    int warp = (blockIdx.x * blockDim.x + threadIdx.x) >> 5;
    int lane = threadIdx.x & 31;
    if (warp >= nrows) return;
    const float4* p = (const float4*)(in + (size_t)warp * in_stride);

    float4 v[8];
    float s = 0.f, ss = 0.f;
#pragma unroll
    for (int i = 0; i < 8; i++) {
        v[i] = p[lane + 32 * i];
        s += v[i].x + v[i].y + v[i].z + v[i].w;
        ss += v[i].x * v[i].x + v[i].y * v[i].y + v[i].z * v[i].z +
              v[i].w * v[i].w;
    }
#pragma unroll
    for (int o = 16; o > 0; o >>= 1) {
        s += __shfl_xor_sync(0xffffffffu, s, o);
        ss += __shfl_xor_sync(0xffffffffu, ss, o);
    }
    float mean = s * (1.0f / Cv);
    float var = ss * (1.0f / Cv) - mean * mean;
    float rstd = rsqrtf(var + 1e-5f);

    const float4* w4 = (const float4*)w;
    const float4* b4 = (const float4*)b;
    OT* op = out + (size_t)warp * out_stride;
#pragma unroll
    for (int i = 0; i < 8; i++) {
        int c = lane + 32 * i;
        float4 wv = w4[c];
        float4 bv = b4[c];
        float y0 = (v[i].x - mean) * rstd * wv.x + bv.x;
        float y1 = (v[i].y - mean) * rstd * wv.y + bv.y;
        float y2 = (v[i].z - mean) * rstd * wv.z + bv.z;
        float y3 = (v[i].w - mean) * rstd * wv.w + bv.w;
        if (sizeof(OT) == 2) {
            uint2 pk;
            pk.x = pack_half2(y0, y1);
            pk.y = pack_half2(y2, y3);
            *(uint2*)(op + c * 4) = pk;
        } else {
            *(float4*)(op + c * 4) = make_float4(y0, y1, y2, y3);
        }
    }
}

// ---------------------------------------------------------------------------
// Dense HGEMM: out = A @ W^T + bias. CTA tile BMT x 128, BK=64, 3-stage
// cp.async pipeline, one barrier/stage. 256 threads, 8 warps (4m x 2n),
// rotating B-fragment buffer. BMT=128 -> 2 CTAs/SM, BMT=64 -> 3 CTAs/SM.
// EPI 0: half out. 1: fp32 residual in-place. 2: gelu half out.
// ---------------------------------------------------------------------------
#define BN 128
#define BKH 64

template <int EPI, int BMT>
__global__ __launch_bounds__(256, (BMT == 64) ? 3 : 2) void hgemm_kernel(
    const __half* __restrict__ A, const __half* __restrict__ W,
    const float* __restrict__ bias, float* __restrict__ resio,
    __half* __restrict__ outh, int M, int N, int K) {
    constexpr int S = 3;
    constexpr int MT = BMT / 64;
    constexpr int ASTG = BMT * BKH;
    constexpr int BSTG = BN * BKH;
    extern __shared__ __align__(16) __half smx[];
    __half* As = smx;
    __half* Bs = smx + S * ASTG;
    const int tid = threadIdx.x;
    const int lane = tid & 31;
    const int w = tid >> 5;
    const int wm = w >> 1;
    const int wn = w & 1;

    const __half* Ab = A + (size_t)(blockIdx.y * BMT) * K;
    const __half* Wb = W + (size_t)(blockIdx.x * BN) * K;
    uint32_t sA = cvta_s(As);
    uint32_t sB = cvta_s(Bs);

    float acc[MT][8][4];
#pragma unroll
    for (int i = 0; i < MT; i++)
#pragma unroll
        for (int j = 0; j < 8; j++)
#pragma unroll
            for (int q = 0; q < 4; q++) acc[i][j][q] = 0.f;

    const int KT = K / BKH;

    auto load_stage = [&](int kt) {
        int stg = kt % S;
        int koff = kt * BKH;
        uint32_t dA = sA + stg * ASTG * 2;
        uint32_t dB = sB + stg * BSTG * 2;
#pragma unroll
        for (int i = 0; i < BMT / 32; i++) {
            int g = tid + i * 256; int r = g >> 3; int c = g & 7;
            cp_async16(dA + sw(r, c * 8) * 2, Ab + (size_t)r * K + koff + c * 8);
        }
#pragma unroll
        for (int i = 0; i < BN / 32; i++) {
            int g = tid + i * 256; int r = g >> 3; int c = g & 7;
            cp_async16(dB + sw(r, c * 8) * 2, Wb + (size_t)r * K + koff + c * 8);
        }
        cp_commit();
    };

    load_stage(0);
    load_stage(1);

    auto bf_addr = [&](uint32_t bB, int k0, int np) -> uint32_t {
        int r = wn * 64 + np * 16 + (lane & 7) + (((lane >> 4) & 1) << 3);
        int kc = k0 + (((lane >> 3) & 1) << 3);
        return bB + sw(r, kc) * 2;
    };

    for (int kt = 0; kt < KT; ++kt) {
        if (kt == KT - 1) cp_wait<0>(); else cp_wait<1>();
        __syncthreads();
        if (kt + 2 < KT) load_stage(kt + 2);

        int stg = kt % S;
        uint32_t aB = sA + (uint32_t)(stg * ASTG * 2);
        uint32_t bB = sB + (uint32_t)(stg * BSTG * 2);
#pragma unroll
        for (int ks = 0; ks < 4; ++ks) {
            int k0 = ks * 16;
            uint32_t af[MT][4];
#pragma unroll
            for (int mt = 0; mt < MT; ++mt) {
                int r = wm * (MT * 16) + mt * 16 + ((lane >> 3) & 1) * 8 + (lane & 7);
                int kc = k0 + ((lane >> 4) << 3);
                ldsm_x4(af[mt][0], af[mt][1], af[mt][2], af[mt][3],
                        aB + sw(r, kc) * 2);
            }
            uint32_t bf0[4];
            ldsm_x4(bf0[0], bf0[1], bf0[2], bf0[3], bf_addr(bB, k0, 0));
#pragma unroll
            for (int np = 0; np < 4; ++np) {
                uint32_t bf1[4];
                if (np < 3)
                    ldsm_x4(bf1[0], bf1[1], bf1[2], bf1[3], bf_addr(bB, k0, np + 1));
#pragma unroll
                for (int mt = 0; mt < MT; ++mt) {
                    mma16816(acc[mt][2 * np], af[mt][0], af[mt][1], af[mt][2],
                             af[mt][3], bf0[0], bf0[1]);
                    mma16816(acc[mt][2 * np + 1], af[mt][0], af[mt][1], af[mt][2],
                             af[mt][3], bf0[2], bf0[3]);
                }
                if (np < 3) {
                    bf0[0] = bf1[0]; bf0[1] = bf1[1];
                    bf0[2] = bf1[2]; bf0[3] = bf1[3];
                }
            }
        }
    }

    int g = lane >> 2, t = lane & 3;
#pragma unroll
    for (int mt = 0; mt < MT; ++mt) {
        int r0 = blockIdx.y * BMT + wm * (MT * 16) + mt * 16 + g;
#pragma unroll
        for (int nt = 0; nt < 8; ++nt) {
            int col = blockIdx.x * BN + wn * 64 + nt * 8 + 2 * t;
            float b0 = bias[col], b1 = bias[col + 1];
            float d0 = acc[mt][nt][0] + b0, d1 = acc[mt][nt][1] + b1;
            float d2 = acc[mt][nt][2] + b0, d3 = acc[mt][nt][3] + b1;
            if (EPI == 0) {
                *(__half2*)&outh[(size_t)r0 * N + col] = __floats2half2_rn(d0, d1);
                *(__half2*)&outh[(size_t)(r0 + 8) * N + col] = __floats2half2_rn(d2, d3);
            } else if (EPI == 1) {
                float2* p0 = (float2*)&resio[(size_t)r0 * N + col];
                float2 v0 = *p0; v0.x += d0; v0.y += d1; *p0 = v0;
                float2* p1 = (float2*)&resio[(size_t)(r0 + 8) * N + col];
                float2 v1 = *p1; v1.x += d2; v1.y += d3; *p1 = v1;
            } else {
                *(__half2*)&outh[(size_t)r0 * N + col] =
                    __floats2half2_rn(gelu_f(d0), gelu_f(d1));
                *(__half2*)&outh[(size_t)(r0 + 8) * N + col] =
                    __floats2half2_rn(gelu_f(d2), gelu_f(d3));
            }
        }
    }
}

// ---------------------------------------------------------------------------
// Fused flash attention (unmasked). Per CTA: 64 q rows of one (b,h).
// 128 threads = 4 warps, occ 3.
// ---------------------------------------------------------------------------
#define FBR 64
#define FBC 128
#define FJT (Tv / FBC)  // 8

__global__ __launch_bounds__(128, 3) void flash_kernel(
    const __half* __restrict__ qkv, __half* __restrict__ o) {
    extern __shared__ __align__(16) __half fsm[];
    __half* Qs = fsm;
    __half* Ks = fsm + FBR * HDv;
    __half* Vs = Ks + 2 * FBC * HDv;
    const uint32_t sQ = cvta_s(Qs), sK = cvta_s(Ks), sV = cvta_s(Vs);
    const int tid = threadIdx.x;
    const int lane = tid & 31;
    const int w = tid >> 5;

    const int z = blockIdx.y, b = z >> 4, h = z & 15;
    const int i0 = blockIdx.x * FBR;
    const __half* qb = qkv + ((size_t)(b * Tv + i0)) * KQKV + h * HDv;
    const __half* kb = qkv + ((size_t)b * Tv) * KQKV + Cv + h * HDv;
    const __half* vb = kb + Cv;

    auto load_kv = [&](int jt) {
        int buf = jt & 1;
        int j0 = jt * FBC;
#pragma unroll
        for (int i = 0; i < 8; i++) {
            int g = tid + i * 128; int r = g >> 3; int c = g & 7;
            cp_async16(sK + (buf * FBC * HDv + sw(r, c * 8)) * 2,
                       kb + (size_t)(j0 + r) * KQKV + c * 8);
            cp_async16(sV + (buf * FBC * HDv + sw(r, c * 8)) * 2,
                       vb + (size_t)(j0 + r) * KQKV + c * 8);
        }
        cp_commit();
    };

#pragma unroll
    for (int i = 0; i < 4; i++) {
        int g = tid + i * 128; int r = g >> 3; int c = g & 7;
        cp_async16(sQ + sw(r, c * 8) * 2, qb + (size_t)r * KQKV + c * 8);
    }
    load_kv(0);

    float m0 = -1e30f, m1 = -1e30f, s0 = 0.f, s1 = 0.f;
    float acc_o[8][4];
#pragma unroll
    for (int i = 0; i < 8; i++)
#pragma unroll
        for (int q = 0; q < 4; q++) acc_o[i][q] = 0.f;

    uint32_t qf[4][4];

    for (int jt = 0; jt < FJT; ++jt) {
        int cur = jt & 1;
        cp_wait<0>();
        __syncthreads();
        if (jt + 1 < FJT) load_kv(jt + 1);

        if (jt == 0) {
#pragma unroll
            for (int ks = 0; ks < 4; ++ks) {
                int r = w * 16 + ((lane >> 3) & 1) * 8 + (lane & 7);
                int kc = ks * 16 + ((lane >> 4) << 3);
                ldsm_x4(qf[ks][0], qf[ks][1], qf[ks][2], qf[ks][3],
                        sQ + sw(r, kc) * 2);
            }
        }

        uint32_t kB = sK + (uint32_t)(cur * FBC * HDv * 2);
        uint32_t vB = sV + (uint32_t)(cur * FBC * HDv * 2);

        float acc_s[16][4];
#pragma unroll
        for (int i = 0; i < 16; i++)
#pragma unroll
            for (int q = 0; q < 4; q++) acc_s[i][q] = 0.f;

#pragma unroll
        for (int ks = 0; ks < 4; ++ks) {
            int k0 = ks * 16;
#pragma unroll
            for (int ntp = 0; ntp < 8; ++ntp) {
                uint32_t b0, b1, b2, b3;
                int r = ntp * 16 + (lane >> 4) * 8 + (lane & 7);
                int kc = k0 + ((lane >> 3) & 1) * 8;
                ldsm_x4(b0, b1, b2, b3, kB + sw(r, kc) * 2);
                mma16816(acc_s[2 * ntp], qf[ks][0], qf[ks][1], qf[ks][2],
                         qf[ks][3], b0, b1);
                mma16816(acc_s[2 * ntp + 1], qf[ks][0], qf[ks][1], qf[ks][2],
                         qf[ks][3], b2, b3);
            }
        }

        float m0n = m0, m1n = m1;
#pragma unroll
        for (int nt = 0; nt < 16; ++nt) {
            acc_s[nt][0] *= 0.125f; acc_s[nt][1] *= 0.125f;
            acc_s[nt][2] *= 0.125f; acc_s[nt][3] *= 0.125f;
            m0n = fmaxf(m0n, fmaxf(acc_s[nt][0], acc_s[nt][1]));
            m1n = fmaxf(m1n, fmaxf(acc_s[nt][2], acc_s[nt][3]));
        }
#pragma unroll
        for (int off = 1; off <= 2; off <<= 1) {
            m0n = fmaxf(m0n, __shfl_xor_sync(0xffffffffu, m0n, off));
            m1n = fmaxf(m1n, __shfl_xor_sync(0xffffffffu, m1n, off));
        }
        float alpha0 = __expf(m0 - m0n);
        float alpha1 = __expf(m1 - m1n);
        m0 = m0n; m1 = m1n;

        float r0 = 0.f, r1 = 0.f;
#pragma unroll
        for (int nt = 0; nt < 16; ++nt) {
            acc_s[nt][0] = __expf(acc_s[nt][0] - m0n);
            acc_s[nt][1] = __expf(acc_s[nt][1] - m0n);
            acc_s[nt][2] = __expf(acc_s[nt][2] - m1n);
            acc_s[nt][3] = __expf(acc_s[nt][3] - m1n);
            r0 += acc_s[nt][0] + acc_s[nt][1];
            r1 += acc_s[nt][2] + acc_s[nt][3];
        }
#pragma unroll
        for (int off = 1; off <= 2; off <<= 1) {
            r0 += __shfl_xor_sync(0xffffffffu, r0, off);
            r1 += __shfl_xor_sync(0xffffffffu, r1, off);
        }
        s0 = s0 * alpha0 + r0;
        s1 = s1 * alpha1 + r1;

#pragma unroll
        for (int nt = 0; nt < 8; ++nt) {
            acc_o[nt][0] *= alpha0; acc_o[nt][1] *= alpha0;
            acc_o[nt][2] *= alpha1; acc_o[nt][3] *= alpha1;
        }

#pragma unroll
        for (int kc = 0; kc < 8; ++kc) {
            uint32_t a0 = pack_half2(acc_s[2 * kc][0], acc_s[2 * kc][1]);
            uint32_t a1 = pack_half2(acc_s[2 * kc][2], acc_s[2 * kc][3]);
            uint32_t a2 = pack_half2(acc_s[2 * kc + 1][0], acc_s[2 * kc + 1][1]);
            uint32_t a3 = pack_half2(acc_s[2 * kc + 1][2], acc_s[2 * kc + 1][3]);
#pragma unroll
            for (int dp = 0; dp < 4; ++dp) {
                uint32_t b0, b1, b2, b3;
                int r = kc * 16 + ((lane >> 3) & 1) * 8 + (lane & 7);
                int c = dp * 16 + (lane >> 4) * 8;
                ldsm_x4t(b0, b1, b2, b3, vB + sw(r, c) * 2);
                mma16816(acc_o[2 * dp], a0, a1, a2, a3, b0, b1);
                mma16816(acc_o[2 * dp + 1], a0, a1, a2, a3, b2, b3);
            }
        }
    }

    float inv0 = 1.0f / s0, inv1 = 1.0f / s1;
    int g = lane >> 2, t = lane & 3;
    int ro0 = i0 + w * 16 + g;
#pragma unroll
    for (int nt = 0; nt < 8; ++nt) {
        int d = nt * 8 + 2 * t;
        *(__half2*)&o[((size_t)b * Tv + ro0) * Cv + h * HDv + d] =
            __floats2half2_rn(acc_o[nt][0] * inv0, acc_o[nt][1] * inv0);
        *(__half2*)&o[((size_t)b * Tv + ro0 + 8) * Cv + h * HDv + d] =
            __floats2half2_rn(acc_o[nt][2] * inv1, acc_o[nt][3] * inv1);
    }
}

// ---------------------------------------------------------------------------
// logits GEMV (fp32, tied wte). One warp per vocab row, both batch rows.
// ---------------------------------------------------------------------------
__global__ void logits_kernel(const float* __restrict__ xf,
                              const float* __restrict__ wte,
                              float* __restrict__ out) {
    int warp = (blockIdx.x * blockDim.x + threadIdx.x) >> 5;
    int lane = threadIdx.x & 31;
    if (warp >= Vv) return;
    const float4* w4 = (const float4*)(wte + (size_t)warp * Cv);
    const float4* x0 = (const float4*)xf;
    const float4* x1 = (const float4*)(xf + Cv);
    float s0 = 0.f, s1 = 0.f;
#pragma unroll
    for (int i = lane; i < Cv / 4; i += 32) {
        float4 w = w4[i];
        float4 a = x0[i];
        float4 c = x1[i];
        s0 += w.x * a.x + w.y * a.y + w.z * a.z + w.w * a.w;
        s1 += w.x * c.x + w.y * c.y + w.z * c.z + w.w * c.w;
    }
#pragma unroll
    for (int o = 16; o > 0; o >>= 1) {
        s0 += __shfl_down_sync(0xffffffffu, s0, o);
        s1 += __shfl_down_sync(0xffffffffu, s1, o);
    }
    if (lane == 0) {
        out[warp] = s0;
        out[Vv + warp] = s1;
    }
}

// ---------------------------------------------------------------------------
extern "C" void kernel_launch(void* const* d_in, const int* in_sizes, int n_in,
                              void* d_out, int out_size) {
    const int* idx = (const int*)d_in[0];
    const float* wte = (const float*)d_in[1];
    const float* wpe = (const float*)d_in[2];
    const float* ln1_w = (const float*)d_in[3];
    const float* ln1_b = (const float*)d_in[4];
    const float* attn_w = (const float*)d_in[5];
    const float* attn_b = (const float*)d_in[6];
    const float* proj_w = (const float*)d_in[7];
    const float* proj_b = (const float*)d_in[8];
    const float* ln2_w = (const float*)d_in[9];
    const float* ln2_b = (const float*)d_in[10];
    const float* fc_w = (const float*)d_in[11];
    const float* fc_b = (const float*)d_in[12];
    const float* fc2_w = (const float*)d_in[13];
    const float* fc2_b = (const float*)d_in[14];
    const float* lnf_w = (const float*)d_in[15];
    const float* lnf_b = (const float*)d_in[16];
    float* out = (float*)d_out;

    float* x;    cudaGetSymbolAddress((void**)&x, g_x);
    __half* ln;  cudaGetSymbolAddress((void**)&ln, g_ln);
    __half* qkv; cudaGetSymbolAddress((void**)&qkv, g_qkv);
    __half* o;   cudaGetSymbolAddress((void**)&o, g_o);
    __half* fc;  cudaGetSymbolAddress((void**)&fc, g_fc);
    float* xf;   cudaGetSymbolAddress((void**)&xf, g_xf);
    __half* wa;  cudaGetSymbolAddress((void**)&wa, g_wa);
    __half* wp;  cudaGetSymbolAddress((void**)&wp, g_wp);
    __half* wf;  cudaGetSymbolAddress((void**)&wf, g_wf);
    __half* wf2; cudaGetSymbolAddress((void**)&wf2, g_wf2);

    const int HSM128 = 3 * (128 * BKH + BN * BKH) * 2;  // 98304
    const int HSM64 = 3 * (64 * BKH + BN * BKH) * 2;    // 73728
    const int FSM = (FBR * HDv + 4 * FBC * HDv) * 2;    // 73728
    cudaFuncSetAttribute(hgemm_kernel<0, 128>, cudaFuncAttributeMaxDynamicSharedMemorySize, HSM128);
    cudaFuncSetAttribute(hgemm_kernel<2, 128>, cudaFuncAttributeMaxDynamicSharedMemorySize, HSM128);
    cudaFuncSetAttribute(hgemm_kernel<1, 64>, cudaFuncAttributeMaxDynamicSharedMemorySize, HSM64);
    cudaFuncSetAttribute(flash_kernel, cudaFuncAttributeMaxDynamicSharedMemorySize, FSM);

    {
        int threads_needed = N4TOT / 2;
        f2h_all_kernel<<<(threads_needed + 255) / 256, 256>>>(
            attn_w, wa, proj_w, wp, fc_w, wf, fc2_w, wf2);
    }

    embed_kernel<<<BTv, 256>>>(idx, wte, wpe, x);

    for (int l = 0; l < Lv; ++l) {
        layernorm_kernel<__half><<<BTv / 8, 256>>>(x, Cv, ln1_w + l * Cv,
                                                   ln1_b + l * Cv, ln, Cv, BTv);
        hgemm_kernel<0, 128><<<dim3(3 * Cv / BN, BTv / 128), 256, HSM128>>>(
            ln, wa + (size_t)l * 3 * Cv * Cv, attn_b + l * 3 * Cv, nullptr, qkv,
            BTv, 3 * Cv, Cv);
        flash_kernel<<<dim3(Tv / FBR, Bv * Hv), 128, FSM>>>(qkv, o);
        hgemm_kernel<1, 64><<<dim3(Cv / BN, BTv / 64), 256, HSM64>>>(
            o, wp + (size_t)l * Cv * Cv, proj_b + l * Cv, x, nullptr, BTv, Cv, Cv);
        layernorm_kernel<__half><<<BTv / 8, 256>>>(x, Cv, ln2_w + l * Cv,
                                                   ln2_b + l * Cv, ln, Cv, BTv);
        hgemm_kernel<2, 128><<<dim3(4 * Cv / BN, BTv / 128), 256, HSM128>>>(
            ln, wf + (size_t)l * 4 * Cv * Cv, fc_b + l * 4 * Cv, nullptr, fc, BTv,
            4 * Cv, Cv);
        hgemm_kernel<1, 64><<<dim3(Cv / BN, BTv / 64), 256, HSM64>>>(
            fc, wf2 + (size_t)l * 4 * Cv * Cv, fc2_b + l * Cv, x, nullptr, BTv, Cv,
            4 * Cv);
    }

    // final LN on the two last-position rows (one block, 2 warps active)
    layernorm_kernel<float><<<1, 256>>>(x + (size_t)(Tv - 1) * Cv, (size_t)Tv * Cv,
                                        lnf_w, lnf_b, xf, Cv, Bv);
    int blocks = (Vv * 32 + 255) / 256;
    logits_kernel<<<blocks, 256>>>(xf, wte, out);
}

// round 17
// speedup vs baseline: 1.0101x; 1.0035x over previous
#include <cuda_runtime.h>
#include <cuda_fp16.h>
#include <math.h>
#include <stdint.h>

// ---------------------------------------------------------------------------
// GPT forward. fp16 mma.sync tensor cores, 3-stage pipelined GEMM.
// qkv/fc: 128x128 CTA tile @ 2 CTAs/SM. proj/fc2: 64x128 @ 3 CTAs/SM.
// Flash attn 64 q-rows @ occ 3. f2h STG.128. Warp-per-row layernorm.
// Fused embed+LN1(layer0). B=2,T=1024,C=1024,L=4,H=16,HD=64,V=50257.
// ---------------------------------------------------------------------------

#define Bv 2
#define Tv 1024
#define Cv 1024
#define Lv 4
#define Hv 16
#define HDv 64
#define Vv 50257
#define BTv 2048
#define KQKV (3 * Cv)

// ---- scratch ---------------------------------------------------------------
__device__ float  g_x[BTv * Cv];
__device__ __half g_ln[BTv * Cv];
__device__ __half g_qkv[BTv * 3 * Cv];
__device__ __half g_o[BTv * Cv];
__device__ __half g_fc[BTv * 4 * Cv];
__device__ float  g_xf[Bv * Cv];
__device__ __half g_wa[Lv * 3 * Cv * Cv];
__device__ __half g_wp[Lv * Cv * Cv];
__device__ __half g_wf[Lv * 4 * Cv * Cv];
__device__ __half g_wf2[Lv * 4 * Cv * Cv];

// ---- PTX helpers ------------------------------------------------------------
__device__ __forceinline__ uint32_t cvta_s(const void* p) {
    return (uint32_t)__cvta_generic_to_shared(p);
}
__device__ __forceinline__ void cp_async16(uint32_t s, const void* g) {
    asm volatile("cp.async.cg.shared.global [%0], [%1], 16;" ::"r"(s), "l"(g));
}
__device__ __forceinline__ void cp_commit() {
    asm volatile("cp.async.commit_group;");
}
template <int N>
__device__ __forceinline__ void cp_wait() {
    asm volatile("cp.async.wait_group %0;" ::"n"(N));
}
__device__ __forceinline__ void ldsm_x4(uint32_t& r0, uint32_t& r1, uint32_t& r2,
                                        uint32_t& r3, uint32_t a) {
    asm volatile("ldmatrix.sync.aligned.m8n8.x4.shared.b16 {%0,%1,%2,%3}, [%4];"
                 : "=r"(r0), "=r"(r1), "=r"(r2), "=r"(r3) : "r"(a));
}
__device__ __forceinline__ void ldsm_x4t(uint32_t& r0, uint32_t& r1, uint32_t& r2,
                                         uint32_t& r3, uint32_t a) {
    asm volatile("ldmatrix.sync.aligned.m8n8.x4.trans.shared.b16 {%0,%1,%2,%3}, [%4];"
                 : "=r"(r0), "=r"(r1), "=r"(r2), "=r"(r3) : "r"(a));
}
__device__ __forceinline__ void mma16816(float* c, uint32_t a0, uint32_t a1,
                                         uint32_t a2, uint32_t a3, uint32_t b0,
                                         uint32_t b1) {
    asm volatile(
        "mma.sync.aligned.m16n8k16.row.col.f32.f16.f16.f32 "
        "{%0,%1,%2,%3}, {%4,%5,%6,%7}, {%8,%9}, {%0,%1,%2,%3};"
        : "+f"(c[0]), "+f"(c[1]), "+f"(c[2]), "+f"(c[3])
        : "r"(a0), "r"(a1), "r"(a2), "r"(a3), "r"(b0), "r"(b1));
}
__device__ __forceinline__ uint32_t pack_half2(float a, float b) {
    __half2 h = __floats2half2_rn(a, b);
    return *reinterpret_cast<uint32_t*>(&h);
}
// swizzled half-offset; tile row = 64 halves (8 x 16B chunks)
__device__ __forceinline__ uint32_t sw(int row, int kcol) {
    return (uint32_t)((row << 6) + ((((kcol >> 3) ^ (row & 7)) << 3) + (kcol & 7)));
}
__device__ __forceinline__ float gelu_f(float x) {
    return 0.5f * x * (1.0f + erff(x * 0.70710678118654752f));
}

// ---------------------------------------------------------------------------
// fused fp32->fp16 weight conversion: 2 float4 loads -> 1 uint4 store/thread.
// ---------------------------------------------------------------------------
#define N4A (Lv * 3 * Cv * Cv / 4)
#define N4P (Lv * Cv * Cv / 4)
#define N4F (Lv * 4 * Cv * Cv / 4)
#define N4TOT (N4A + N4P + 2 * N4F)

__global__ void f2h_all_kernel(const float* __restrict__ sa, __half* __restrict__ da,
                               const float* __restrict__ sp, __half* __restrict__ dp,
                               const float* __restrict__ sf, __half* __restrict__ df,
                               const float* __restrict__ sf2, __half* __restrict__ df2) {
    int i = (blockIdx.x * blockDim.x + threadIdx.x) * 2;
    if (i >= N4TOT) return;
    const float* s;
    __half* d;
    if (i < N4A) {
        s = sa; d = da;
    } else if (i < N4A + N4P) {
        i -= N4A; s = sp; d = dp;
    } else if (i < N4A + N4P + N4F) {
        i -= N4A + N4P; s = sf; d = df;
    } else {
        i -= N4A + N4P + N4F; s = sf2; d = df2;
    }
    const float4* s4 = (const float4*)s;
    float4 v0 = s4[i], v1 = s4[i + 1];
    uint4 pk;
    pk.x = pack_half2(v0.x, v0.y);
    pk.y = pack_half2(v0.z, v0.w);
    pk.z = pack_half2(v1.x, v1.y);
    pk.w = pack_half2(v1.z, v1.w);
    *(uint4*)(d + (size_t)i * 4) = pk;
}

// ---------------------------------------------------------------------------
// Fused embed + LN1(layer 0). Warp per row: x = wte[idx]+wpe[t] (written fp32)
// and ln = LN(x; w,b) (written fp16). 8 rows/block.
// ---------------------------------------------------------------------------
__global__ __launch_bounds__(256) void embed_ln_kernel(
    const int* __restrict__ idx, const float* __restrict__ wte,
    const float* __restrict__ wpe, const float* __restrict__ w,
    const float* __restrict__ b, float* __restrict__ x,
    __half* __restrict__ ln) {
    int row = (blockIdx.x * blockDim.x + threadIdx.x) >> 5;
    int lane = threadIdx.x & 31;
    if (row >= BTv) return;
    int t = row & (Tv - 1);
    int tok = idx[row];
    const float4* a4 = (const float4*)(wte + (size_t)tok * Cv);
    const float4* p4 = (const float4*)(wpe + (size_t)t * Cv);
    float4* x4 = (float4*)(x + (size_t)row * Cv);

    float4 v[8];
    float s = 0.f, ss = 0.f;
#pragma unroll
    for (int i = 0; i < 8; i++) {
        int c = lane + 32 * i;
        float4 a = a4[c];
        float4 p = p4[c];
        v[i] = make_float4(a.x + p.x, a.y + p.y, a.z + p.z, a.w + p.w);
        x4[c] = v[i];
        s += v[i].x + v[i].y + v[i].z + v[i].w;
        ss += v[i].x * v[i].x + v[i].y * v[i].y + v[i].z * v[i].z +
              v[i].w * v[i].w;
    }
#pragma unroll
    for (int o = 16; o > 0; o >>= 1) {
        s += __shfl_xor_sync(0xffffffffu, s, o);
        ss += __shfl_xor_sync(0xffffffffu, ss, o);
    }
    float mean = s * (1.0f / Cv);
    float var = ss * (1.0f / Cv) - mean * mean;
    float rstd = rsqrtf(var + 1e-5f);

    const float4* w4 = (const float4*)w;
    const float4* b4 = (const float4*)b;
    __half* op = ln + (size_t)row * Cv;
#pragma unroll
    for (int i = 0; i < 8; i++) {
        int c = lane + 32 * i;
        float4 wv = w4[c];
        float4 bv = b4[c];
        uint2 pk;
        pk.x = pack_half2((v[i].x - mean) * rstd * wv.x + bv.x,
                          (v[i].y - mean) * rstd * wv.y + bv.y);
        pk.y = pack_half2((v[i].z - mean) * rstd * wv.z + bv.z,
                          (v[i].w - mean) * rstd * wv.w + bv.w);
        *(uint2*)(op + c * 4) = pk;
    }
}

// ---------------------------------------------------------------------------
// Warp-per-row layernorm: 8 warps/block = 8 rows, grid = rows/8.
// ---------------------------------------------------------------------------
template <typename OT>
__global__ __launch_bounds__(256) void layernorm_kernel(
    const float* __restrict__ in, size_t in_stride, const float* __restrict__ w,
    const float* __restrict__ b, OT* __restrict__ out, size_t out_stride,
    int nrows) {
    int warp = (blockIdx.x * blockDim.x + threadIdx.x) >> 5;
    int lane = threadIdx.x & 31;
    if (warp >= nrows) return;
    const float4* p = (const float4*)(in + (size_t)warp * in_stride);

    float4 v[8];
    float s = 0.f, ss = 0.f;
#pragma unroll
    for (int i = 0; i < 8; i++) {
        v[i] = p[lane + 32 * i];
        s += v[i].x + v[i].y + v[i].z + v[i].w;
        ss += v[i].x * v[i].x + v[i].y * v[i].y + v[i].z * v[i].z +
              v[i].w * v[i].w;
    }
#pragma unroll
    for (int o = 16; o > 0; o >>= 1) {
        s += __shfl_xor_sync(0xffffffffu, s, o);
        ss += __shfl_xor_sync(0xffffffffu, ss, o);
    }
    float mean = s * (1.0f / Cv);
    float var = ss * (1.0f / Cv) - mean * mean;
    float rstd = rsqrtf(var + 1e-5f);

    const float4* w4 = (const float4*)w;
    const float4* b4 = (const float4*)b;
    OT* op = out + (size_t)warp * out_stride;
#pragma unroll
    for (int i = 0; i < 8; i++) {
        int c = lane + 32 * i;
        float4 wv = w4[c];
        float4 bv = b4[c];
        float y0 = (v[i].x - mean) * rstd * wv.x + bv.x;
        float y1 = (v[i].y - mean) * rstd * wv.y + bv.y;
        float y2 = (v[i].z - mean) * rstd * wv.z + bv.z;
        float y3 = (v[i].w - mean) * rstd * wv.w + bv.w;
        if (sizeof(OT) == 2) {
            uint2 pk;
            pk.x = pack_half2(y0, y1);
            pk.y = pack_half2(y2, y3);
            *(uint2*)(op + c * 4) = pk;
        } else {
            *(float4*)(op + c * 4) = make_float4(y0, y1, y2, y3);
        }
    }
}

// ---------------------------------------------------------------------------
// Dense HGEMM: out = A @ W^T + bias. CTA tile BMT x 128, BK=64, 3-stage
// cp.async pipeline, one barrier/stage. 256 threads, 8 warps (4m x 2n),
// rotating B-fragment buffer. BMT=128 -> 2 CTAs/SM, BMT=64 -> 3 CTAs/SM.
// EPI 0: half out. 1: fp32 residual in-place. 2: gelu half out.
// ---------------------------------------------------------------------------
#define BN 128
#define BKH 64

template <int EPI, int BMT>
__global__ __launch_bounds__(256, (BMT == 64) ? 3 : 2) void hgemm_kernel(
    const __half* __restrict__ A, const __half* __restrict__ W,
    const float* __restrict__ bias, float* __restrict__ resio,
    __half* __restrict__ outh, int M, int N, int K) {
    constexpr int S = 3;
    constexpr int MT = BMT / 64;
    constexpr int ASTG = BMT * BKH;
    constexpr int BSTG = BN * BKH;
    extern __shared__ __align__(16) __half smx[];
    __half* As = smx;
    __half* Bs = smx + S * ASTG;
    const int tid = threadIdx.x;
    const int lane = tid & 31;
    const int w = tid >> 5;
    const int wm = w >> 1;
    const int wn = w & 1;

    const __half* Ab = A + (size_t)(blockIdx.y * BMT) * K;
    const __half* Wb = W + (size_t)(blockIdx.x * BN) * K;
    uint32_t sA = cvta_s(As);
    uint32_t sB = cvta_s(Bs);

    float acc[MT][8][4];
#pragma unroll
    for (int i = 0; i < MT; i++)
#pragma unroll
        for (int j = 0; j < 8; j++)
#pragma unroll
            for (int q = 0; q < 4; q++) acc[i][j][q] = 0.f;

    const int KT = K / BKH;

    auto load_stage = [&](int kt) {
        int stg = kt % S;
        int koff = kt * BKH;
        uint32_t dA = sA + stg * ASTG * 2;
        uint32_t dB = sB + stg * BSTG * 2;
#pragma unroll
        for (int i = 0; i < BMT / 32; i++) {
            int g = tid + i * 256; int r = g >> 3; int c = g & 7;
            cp_async16(dA + sw(r, c * 8) * 2, Ab + (size_t)r * K + koff + c * 8);
        }
#pragma unroll
        for (int i = 0; i < BN / 32; i++) {
            int g = tid + i * 256; int r = g >> 3; int c = g & 7;
            cp_async16(dB + sw(r, c * 8) * 2, Wb + (size_t)r * K + koff + c * 8);
        }
        cp_commit();
    };

    load_stage(0);
    load_stage(1);

    auto bf_addr = [&](uint32_t bB, int k0, int np) -> uint32_t {
        int r = wn * 64 + np * 16 + (lane & 7) + (((lane >> 4) & 1) << 3);
        int kc = k0 + (((lane >> 3) & 1) << 3);
        return bB + sw(r, kc) * 2;
    };

    for (int kt = 0; kt < KT; ++kt) {
        if (kt == KT - 1) cp_wait<0>(); else cp_wait<1>();
        __syncthreads();
        if (kt + 2 < KT) load_stage(kt + 2);

        int stg = kt % S;
        uint32_t aB = sA + (uint32_t)(stg * ASTG * 2);
        uint32_t bB = sB + (uint32_t)(stg * BSTG * 2);
#pragma unroll
        for (int ks = 0; ks < 4; ++ks) {
            int k0 = ks * 16;
            uint32_t af[MT][4];
#pragma unroll
            for (int mt = 0; mt < MT; ++mt) {
                int r = wm * (MT * 16) + mt * 16 + ((lane >> 3) & 1) * 8 + (lane & 7);
                int kc = k0 + ((lane >> 4) << 3);
                ldsm_x4(af[mt][0], af[mt][1], af[mt][2], af[mt][3],
                        aB + sw(r, kc) * 2);
            }
            uint32_t bf0[4];
            ldsm_x4(bf0[0], bf0[1], bf0[2], bf0[3], bf_addr(bB, k0, 0));
#pragma unroll
            for (int np = 0; np < 4; ++np) {
                uint32_t bf1[4];
                if (np < 3)
                    ldsm_x4(bf1[0], bf1[1], bf1[2], bf1[3], bf_addr(bB, k0, np + 1));
#pragma unroll
                for (int mt = 0; mt < MT; ++mt) {
                    mma16816(acc[mt][2 * np], af[mt][0], af[mt][1], af[mt][2],
                             af[mt][3], bf0[0], bf0[1]);
                    mma16816(acc[mt][2 * np + 1], af[mt][0], af[mt][1], af[mt][2],
                             af[mt][3], bf0[2], bf0[3]);
                }
                if (np < 3) {
                    bf0[0] = bf1[0]; bf0[1] = bf1[1];
                    bf0[2] = bf1[2]; bf0[3] = bf1[3];
                }
            }
        }
    }

    int g = lane >> 2, t = lane & 3;
#pragma unroll
    for (int mt = 0; mt < MT; ++mt) {
        int r0 = blockIdx.y * BMT + wm * (MT * 16) + mt * 16 + g;
#pragma unroll
        for (int nt = 0; nt < 8; ++nt) {
            int col = blockIdx.x * BN + wn * 64 + nt * 8 + 2 * t;
            float b0 = bias[col], b1 = bias[col + 1];
            float d0 = acc[mt][nt][0] + b0, d1 = acc[mt][nt][1] + b1;
            float d2 = acc[mt][nt][2] + b0, d3 = acc[mt][nt][3] + b1;
            if (EPI == 0) {
                *(__half2*)&outh[(size_t)r0 * N + col] = __floats2half2_rn(d0, d1);
                *(__half2*)&outh[(size_t)(r0 + 8) * N + col] = __floats2half2_rn(d2, d3);
            } else if (EPI == 1) {
                float2* p0 = (float2*)&resio[(size_t)r0 * N + col];
                float2 v0 = *p0; v0.x += d0; v0.y += d1; *p0 = v0;
                float2* p1 = (float2*)&resio[(size_t)(r0 + 8) * N + col];
                float2 v1 = *p1; v1.x += d2; v1.y += d3; *p1 = v1;
            } else {
                *(__half2*)&outh[(size_t)r0 * N + col] =
                    __floats2half2_rn(gelu_f(d0), gelu_f(d1));
                *(__half2*)&outh[(size_t)(r0 + 8) * N + col] =
                    __floats2half2_rn(gelu_f(d2), gelu_f(d3));
            }
        }
    }
}

// ---------------------------------------------------------------------------
// Fused flash attention (unmasked). Per CTA: 64 q rows of one (b,h).
// 128 threads = 4 warps, occ 3.
// ---------------------------------------------------------------------------
#define FBR 64
#define FBC 128
#define FJT (Tv / FBC)  // 8

__global__ __launch_bounds__(128, 3) void flash_kernel(
    const __half* __restrict__ qkv, __half* __restrict__ o) {
    extern __shared__ __align__(16) __half fsm[];
    __half* Qs = fsm;
    __half* Ks = fsm + FBR * HDv;
    __half* Vs = Ks + 2 * FBC * HDv;
    const uint32_t sQ = cvta_s(Qs), sK = cvta_s(Ks), sV = cvta_s(Vs);
    const int tid = threadIdx.x;
    const int lane = tid & 31;
    const int w = tid >> 5;

    const int z = blockIdx.y, b = z >> 4, h = z & 15;
    const int i0 = blockIdx.x * FBR;
    const __half* qb = qkv + ((size_t)(b * Tv + i0)) * KQKV + h * HDv;
    const __half* kb = qkv + ((size_t)b * Tv) * KQKV + Cv + h * HDv;
    const __half* vb = kb + Cv;

    auto load_kv = [&](int jt) {
        int buf = jt & 1;
        int j0 = jt * FBC;
#pragma unroll
        for (int i = 0; i < 8; i++) {
            int g = tid + i * 128; int r = g >> 3; int c = g & 7;
            cp_async16(sK + (buf * FBC * HDv + sw(r, c * 8)) * 2,
                       kb + (size_t)(j0 + r) * KQKV + c * 8);
            cp_async16(sV + (buf * FBC * HDv + sw(r, c * 8)) * 2,
                       vb + (size_t)(j0 + r) * KQKV + c * 8);
        }
        cp_commit();
    };

#pragma unroll
    for (int i = 0; i < 4; i++) {
        int g = tid + i * 128; int r = g >> 3; int c = g & 7;
        cp_async16(sQ + sw(r, c * 8) * 2, qb + (size_t)r * KQKV + c * 8);
    }
    load_kv(0);

    float m0 = -1e30f, m1 = -1e30f, s0 = 0.f, s1 = 0.f;
    float acc_o[8][4];
#pragma unroll
    for (int i = 0; i < 8; i++)
#pragma unroll
        for (int q = 0; q < 4; q++) acc_o[i][q] = 0.f;

    uint32_t qf[4][4];

    for (int jt = 0; jt < FJT; ++jt) {
        int cur = jt & 1;
        cp_wait<0>();
        __syncthreads();
        if (jt + 1 < FJT) load_kv(jt + 1);

        if (jt == 0) {
#pragma unroll
            for (int ks = 0; ks < 4; ++ks) {
                int r = w * 16 + ((lane >> 3) & 1) * 8 + (lane & 7);
                int kc = ks * 16 + ((lane >> 4) << 3);
                ldsm_x4(qf[ks][0], qf[ks][1], qf[ks][2], qf[ks][3],
                        sQ + sw(r, kc) * 2);
            }
        }

        uint32_t kB = sK + (uint32_t)(cur * FBC * HDv * 2);
        uint32_t vB = sV + (uint32_t)(cur * FBC * HDv * 2);

        float acc_s[16][4];
#pragma unroll
        for (int i = 0; i < 16; i++)
#pragma unroll
            for (int q = 0; q < 4; q++) acc_s[i][q] = 0.f;

#pragma unroll
        for (int ks = 0; ks < 4; ++ks) {
            int k0 = ks * 16;
#pragma unroll
            for (int ntp = 0; ntp < 8; ++ntp) {
                uint32_t b0, b1, b2, b3;
                int r = ntp * 16 + (lane >> 4) * 8 + (lane & 7);
                int kc = k0 + ((lane >> 3) & 1) * 8;
                ldsm_x4(b0, b1, b2, b3, kB + sw(r, kc) * 2);
                mma16816(acc_s[2 * ntp], qf[ks][0], qf[ks][1], qf[ks][2],
                         qf[ks][3], b0, b1);
                mma16816(acc_s[2 * ntp + 1], qf[ks][0], qf[ks][1], qf[ks][2],
                         qf[ks][3], b2, b3);
            }
        }

        float m0n = m0, m1n = m1;
#pragma unroll
        for (int nt = 0; nt < 16; ++nt) {
            acc_s[nt][0] *= 0.125f; acc_s[nt][1] *= 0.125f;
            acc_s[nt][2] *= 0.125f; acc_s[nt][3] *= 0.125f;
            m0n = fmaxf(m0n, fmaxf(acc_s[nt][0], acc_s[nt][1]));
            m1n = fmaxf(m1n, fmaxf(acc_s[nt][2], acc_s[nt][3]));
        }
#pragma unroll
        for (int off = 1; off <= 2; off <<= 1) {
            m0n = fmaxf(m0n, __shfl_xor_sync(0xffffffffu, m0n, off));
            m1n = fmaxf(m1n, __shfl_xor_sync(0xffffffffu, m1n, off));
        }
        float alpha0 = __expf(m0 - m0n);
        float alpha1 = __expf(m1 - m1n);
        m0 = m0n; m1 = m1n;

        float r0 = 0.f, r1 = 0.f;
#pragma unroll
        for (int nt = 0; nt < 16; ++nt) {
            acc_s[nt][0] = __expf(acc_s[nt][0] - m0n);
            acc_s[nt][1] = __expf(acc_s[nt][1] - m0n);
            acc_s[nt][2] = __expf(acc_s[nt][2] - m1n);
            acc_s[nt][3] = __expf(acc_s[nt][3] - m1n);
            r0 += acc_s[nt][0] + acc_s[nt][1];
            r1 += acc_s[nt][2] + acc_s[nt][3];
        }
#pragma unroll
        for (int off = 1; off <= 2; off <<= 1) {
            r0 += __shfl_xor_sync(0xffffffffu, r0, off);
            r1 += __shfl_xor_sync(0xffffffffu, r1, off);
        }
        s0 = s0 * alpha0 + r0;
        s1 = s1 * alpha1 + r1;

#pragma unroll
        for (int nt = 0; nt < 8; ++nt) {
            acc_o[nt][0] *= alpha0; acc_o[nt][1] *= alpha0;
            acc_o[nt][2] *= alpha1; acc_o[nt][3] *= alpha1;
        }

#pragma unroll
        for (int kc = 0; kc < 8; ++kc) {
            uint32_t a0 = pack_half2(acc_s[2 * kc][0], acc_s[2 * kc][1]);
            uint32_t a1 = pack_half2(acc_s[2 * kc][2], acc_s[2 * kc][3]);
            uint32_t a2 = pack_half2(acc_s[2 * kc + 1][0], acc_s[2 * kc + 1][1]);
            uint32_t a3 = pack_half2(acc_s[2 * kc + 1][2], acc_s[2 * kc + 1][3]);
#pragma unroll
            for (int dp = 0; dp < 4; ++dp) {
                uint32_t b0, b1, b2, b3;
                int r = kc * 16 + ((lane >> 3) & 1) * 8 + (lane & 7);
                int c = dp * 16 + (lane >> 4) * 8;
                ldsm_x4t(b0, b1, b2, b3, vB + sw(r, c) * 2);
                mma16816(acc_o[2 * dp], a0, a1, a2, a3, b0, b1);
                mma16816(acc_o[2 * dp + 1], a0, a1, a2, a3, b2, b3);
            }
        }
    }

    float inv0 = 1.0f / s0, inv1 = 1.0f / s1;
    int g = lane >> 2, t = lane & 3;
    int ro0 = i0 + w * 16 + g;
#pragma unroll
    for (int nt = 0; nt < 8; ++nt) {
        int d = nt * 8 + 2 * t;
        *(__half2*)&o[((size_t)b * Tv + ro0) * Cv + h * HDv + d] =
            __floats2half2_rn(acc_o[nt][0] * inv0, acc_o[nt][1] * inv0);
        *(__half2*)&o[((size_t)b * Tv + ro0 + 8) * Cv + h * HDv + d] =
            __floats2half2_rn(acc_o[nt][2] * inv1, acc_o[nt][3] * inv1);
    }
}

// ---------------------------------------------------------------------------
// logits GEMV (fp32, tied wte). One warp per vocab row, both batch rows.
// ---------------------------------------------------------------------------
__global__ void logits_kernel(const float* __restrict__ xf,
                              const float* __restrict__ wte,
                              float* __restrict__ out) {
    int warp = (blockIdx.x * blockDim.x + threadIdx.x) >> 5;
    int lane = threadIdx.x & 31;
    if (warp >= Vv) return;
    const float4* w4 = (const float4*)(wte + (size_t)warp * Cv);
    const float4* x0 = (const float4*)xf;
    const float4* x1 = (const float4*)(xf + Cv);
    float s0 = 0.f, s1 = 0.f;
#pragma unroll
    for (int i = lane; i < Cv / 4; i += 32) {
        float4 w = w4[i];
        float4 a = x0[i];
        float4 c = x1[i];
        s0 += w.x * a.x + w.y * a.y + w.z * a.z + w.w * a.w;
        s1 += w.x * c.x + w.y * c.y + w.z * c.z + w.w * c.w;
    }
#pragma unroll
    for (int o = 16; o > 0; o >>= 1) {
        s0 += __shfl_down_sync(0xffffffffu, s0, o);
        s1 += __shfl_down_sync(0xffffffffu, s1, o);
    }
    if (lane == 0) {
        out[warp] = s0;
        out[Vv + warp] = s1;
    }
}

// ---------------------------------------------------------------------------
extern "C" void kernel_launch(void* const* d_in, const int* in_sizes, int n_in,
                              void* d_out, int out_size) {
    const int* idx = (const int*)d_in[0];
    const float* wte = (const float*)d_in[1];
    const float* wpe = (const float*)d_in[2];
    const float* ln1_w = (const float*)d_in[3];
    const float* ln1_b = (const float*)d_in[4];
    const float* attn_w = (const float*)d_in[5];
    const float* attn_b = (const float*)d_in[6];
    const float* proj_w = (const float*)d_in[7];
    const float* proj_b = (const float*)d_in[8];
    const float* ln2_w = (const float*)d_in[9];
    const float* ln2_b = (const float*)d_in[10];
    const float* fc_w = (const float*)d_in[11];
    const float* fc_b = (const float*)d_in[12];
    const float* fc2_w = (const float*)d_in[13];
    const float* fc2_b = (const float*)d_in[14];
    const float* lnf_w = (const float*)d_in[15];
    const float* lnf_b = (const float*)d_in[16];
    float* out = (float*)d_out;

    float* x;    cudaGetSymbolAddress((void**)&x, g_x);
    __half* ln;  cudaGetSymbolAddress((void**)&ln, g_ln);
    __half* qkv; cudaGetSymbolAddress((void**)&qkv, g_qkv);
    __half* o;   cudaGetSymbolAddress((void**)&o, g_o);
    __half* fc;  cudaGetSymbolAddress((void**)&fc, g_fc);
    float* xf;   cudaGetSymbolAddress((void**)&xf, g_xf);
    __half* wa;  cudaGetSymbolAddress((void**)&wa, g_wa);
    __half* wp;  cudaGetSymbolAddress((void**)&wp, g_wp);
    __half* wf;  cudaGetSymbolAddress((void**)&wf, g_wf);
    __half* wf2; cudaGetSymbolAddress((void**)&wf2, g_wf2);

    const int HSM128 = 3 * (128 * BKH + BN * BKH) * 2;  // 98304
    const int HSM64 = 3 * (64 * BKH + BN * BKH) * 2;    // 73728
    const int FSM = (FBR * HDv + 4 * FBC * HDv) * 2;    // 73728
    cudaFuncSetAttribute(hgemm_kernel<0, 128>, cudaFuncAttributeMaxDynamicSharedMemorySize, HSM128);
    cudaFuncSetAttribute(hgemm_kernel<2, 128>, cudaFuncAttributeMaxDynamicSharedMemorySize, HSM128);
    cudaFuncSetAttribute(hgemm_kernel<1, 64>, cudaFuncAttributeMaxDynamicSharedMemorySize, HSM64);
    cudaFuncSetAttribute(flash_kernel, cudaFuncAttributeMaxDynamicSharedMemorySize, FSM);

    {
        int threads_needed = N4TOT / 2;
        f2h_all_kernel<<<(threads_needed + 255) / 256, 256>>>(
            attn_w, wa, proj_w, wp, fc_w, wf, fc2_w, wf2);
    }

    // fused embed + LN1(layer 0)
    embed_ln_kernel<<<BTv / 8, 256>>>(idx, wte, wpe, ln1_w, ln1_b, x, ln);

    for (int l = 0; l < Lv; ++l) {
        if (l > 0)
            layernorm_kernel<__half><<<BTv / 8, 256>>>(x, Cv, ln1_w + l * Cv,
                                                       ln1_b + l * Cv, ln, Cv, BTv);
        hgemm_kernel<0, 128><<<dim3(3 * Cv / BN, BTv / 128), 256, HSM128>>>(
            ln, wa + (size_t)l * 3 * Cv * Cv, attn_b + l * 3 * Cv, nullptr, qkv,
            BTv, 3 * Cv, Cv);
        flash_kernel<<<dim3(Tv / FBR, Bv * Hv), 128, FSM>>>(qkv, o);
        hgemm_kernel<1, 64><<<dim3(Cv / BN, BTv / 64), 256, HSM64>>>(
            o, wp + (size_t)l * Cv * Cv, proj_b + l * Cv, x, nullptr, BTv, Cv, Cv);
        layernorm_kernel<__half><<<BTv / 8, 256>>>(x, Cv, ln2_w + l * Cv,
                                                   ln2_b + l * Cv, ln, Cv, BTv);
        hgemm_kernel<2, 128><<<dim3(4 * Cv / BN, BTv / 128), 256, HSM128>>>(
            ln, wf + (size_t)l * 4 * Cv * Cv, fc_b + l * 4 * Cv, nullptr, fc, BTv,
            4 * Cv, Cv);
        hgemm_kernel<1, 64><<<dim3(Cv / BN, BTv / 64), 256, HSM64>>>(
            fc, wf2 + (size_t)l * 4 * Cv * Cv, fc2_b + l * Cv, x, nullptr, BTv, Cv,
            4 * Cv);
    }

    // final LN on the two last-position rows (one block, 2 warps active)
    layernorm_kernel<float><<<1, 256>>>(x + (size_t)(Tv - 1) * Cv, (size_t)Tv * Cv,
                                        lnf_w, lnf_b, xf, Cv, Bv);
    int blocks = (Vv * 32 + 255) / 256;
    logits_kernel<<<blocks, 256>>>(xf, wte, out);
}